// round 1
// baseline (speedup 1.0000x reference)
#include <cuda_runtime.h>

#define MAXN 4
#define MAXP 8192
#define BLOCK 256
#define RPT 4
#define TILE (BLOCK * RPT)   // 1024 outer points per block
#define CHUNK 512            // inner points per block

// Scratch (no allocations allowed): packed points {x,y,z, 0.5*|p|^2}, per-point
// running-min keys (monotone uint transform of float), partial sums.
__device__ float4   g_xpack[MAXN * MAXP];
__device__ float4   g_ypack[MAXN * MAXP];
__device__ unsigned g_minx[MAXN * MAXP];
__device__ unsigned g_miny[MAXN * MAXP];
__device__ float    g_partial[MAXN * 2];

// Order-preserving float <-> uint mapping (works for all finite floats, any sign)
static __device__ __forceinline__ unsigned fkey(float f) {
    unsigned u = __float_as_uint(f);
    return (u & 0x80000000u) ? ~u : (u | 0x80000000u);
}
static __device__ __forceinline__ float finv(unsigned u) {
    unsigned v = (u & 0x80000000u) ? (u ^ 0x80000000u) : ~u;
    return __uint_as_float(v);
}

__global__ void pack_kernel(const float* __restrict__ x, const float* __restrict__ y,
                            const int* __restrict__ lens, int n, int p1, int p2) {
    int idx = blockIdx.x * BLOCK + threadIdx.x;
    if (idx < n * p1) {
        float a = x[3 * idx + 0], b = x[3 * idx + 1], c = x[3 * idx + 2];
        float h = 0.5f * (a * a + b * b + c * c);
        g_xpack[idx] = make_float4(a, b, c, h);
        g_minx[idx] = 0xFFFFFFFFu;
    }
    if (idx < n * p2) {
        int b_ = idx / p2;
        int j  = idx - b_ * p2;
        float a = y[3 * idx + 0], bb = y[3 * idx + 1], c = y[3 * idx + 2];
        float h = 0.5f * (a * a + bb * bb + c * c);
        float w = (j < lens[b_]) ? h : 1e18f;  // padded targets can never be the min
        g_ypack[idx] = make_float4(a, bb, c, w);
        g_miny[idx] = 0xFFFFFFFFu;
    }
}

// DIR=0: outer = pred (x), inner = target (y)  -> min over valid j (mask via s=1e18)
// DIR=1: outer = target (y), inner = pred (x)  -> only outer rows j < len matter
// Inner-loop math: min_j d2 = 2 * (h_outer + min_j (h_inner_j - dot_ij))
// => 3 FFMA + 1 FMNMX per pair (h_outer added once at finalize).
template <int DIR>
__global__ void __launch_bounds__(BLOCK) pass_kernel(const int* __restrict__ lens,
                                                     int p_out, int p_in) {
    int b = blockIdx.z;
    int len = lens[b];
    int outer_len = DIR ? len : p_out;
    int inner_len = DIR ? p_in : len;

    int tb = blockIdx.x * TILE;
    if (tb >= outer_len) return;            // whole tile is padded outer rows
    int cb = blockIdx.y * CHUNK;
    if (cb >= inner_len) return;            // whole chunk is padded inner cols
    int ce = min(cb + CHUNK, p_in);

    const float4* __restrict__ opack = DIR ? g_ypack : g_xpack;
    const float4* __restrict__ ipack = DIR ? g_xpack : g_ypack;
    unsigned* mins = DIR ? g_miny : g_minx;

    float ox[RPT], oy[RPT], oz[RPT];
    int oidx[RPT];
#pragma unroll
    for (int r = 0; r < RPT; r++) {
        oidx[r] = tb + threadIdx.x + r * BLOCK;     // p_out % TILE == 0, always in-bounds
        float4 v = opack[b * p_out + oidx[r]];
        ox[r] = v.x; oy[r] = v.y; oz[r] = v.z;
    }
    float m[RPT];
#pragma unroll
    for (int r = 0; r < RPT; r++) m[r] = 3.4e38f;

    const float4* __restrict__ ip = ipack + b * p_in;
#pragma unroll 4
    for (int j = cb; j < ce; ++j) {
        float4 v = __ldg(ip + j);                   // uniform address, L1-hit broadcast
#pragma unroll
        for (int r = 0; r < RPT; r++) {
            float t = fmaf(-ox[r], v.x, v.w);       // h_j - x.x*y.x
            t = fmaf(-oy[r], v.y, t);
            t = fmaf(-oz[r], v.z, t);               // = h_j - dot
            m[r] = fminf(m[r], t);
        }
    }
#pragma unroll
    for (int r = 0; r < RPT; r++)
        if (oidx[r] < outer_len)
            atomicMin(&mins[b * p_out + oidx[r]], fkey(m[r]));
}

__global__ void finalize1(const int* __restrict__ lens, int p1, int p2) {
    int b = blockIdx.x, dir = blockIdx.y;
    __shared__ float sh[BLOCK];
    float acc = 0.f;
    if (dir == 0) {
        for (int i = threadIdx.x; i < p1; i += BLOCK) {
            float d2 = 2.f * (g_xpack[b * p1 + i].w + finv(g_minx[b * p1 + i]));
            acc += fmaxf(d2, 0.f);
        }
    } else {
        int len = lens[b];
        for (int j = threadIdx.x; j < len; j += BLOCK) {
            float d2 = 2.f * (g_ypack[b * p2 + j].w + finv(g_miny[b * p2 + j]));
            acc += fmaxf(d2, 0.f);
        }
    }
    sh[threadIdx.x] = acc;
    __syncthreads();
    for (int s = BLOCK / 2; s > 0; s >>= 1) {
        if (threadIdx.x < s) sh[threadIdx.x] += sh[threadIdx.x + s];
        __syncthreads();
    }
    if (threadIdx.x == 0) {
        float denom = dir ? (float)lens[b] : (float)p1;
        g_partial[b * 2 + dir] = sh[0] / denom;
    }
}

__global__ void finalize2(float* __restrict__ out, int n) {
    float s = 0.f;
    for (int i = 0; i < 2 * n; i++) s += g_partial[i];
    out[0] = s / (float)n;
}

extern "C" void kernel_launch(void* const* d_in, const int* in_sizes, int n_in,
                              void* d_out, int out_size) {
    const float* x   = (const float*)d_in[0];   // pred_points   [N,P1,3] f32
    const float* y   = (const float*)d_in[1];   // target_points [N,P2,3] f32
    const int*  lens = (const int*)d_in[2];     // target_lengths [N] i32
    // d_in[3] = num_neighbours (always 1 per setup; mean over K=1 is identity)

    int n  = in_sizes[2];
    int p1 = in_sizes[0] / (3 * n);
    int p2 = in_sizes[1] / (3 * n);
    int mx = p1 > p2 ? p1 : p2;

    pack_kernel<<<(n * mx + BLOCK - 1) / BLOCK, BLOCK>>>(x, y, lens, n, p1, p2);

    dim3 g0((p1 + TILE - 1) / TILE, (p2 + CHUNK - 1) / CHUNK, n);
    pass_kernel<0><<<g0, BLOCK>>>(lens, p1, p2);

    dim3 g1((p2 + TILE - 1) / TILE, (p1 + CHUNK - 1) / CHUNK, n);
    pass_kernel<1><<<g1, BLOCK>>>(lens, p2, p1);

    finalize1<<<dim3(n, 2), BLOCK>>>(lens, p1, p2);
    finalize2<<<1, 1>>>((float*)d_out, n);
}

// round 2
// speedup vs baseline: 1.3145x; 1.3145x over previous
#include <cuda_runtime.h>

#define MAXN 4
#define MAXP 8192
#define BLOCK 128
#define RPT 8
#define TILE (BLOCK * RPT)   // 1024 outer points per block
#define CHUNK 1024           // inner points per block
#define FSPLIT 8
#define BLOCKF 256

typedef unsigned long long u64;

// SoA scratch: [coord][b*p + i], coord 0=x 1=y 2=z 3=h (h = 0.5*|p|^2; padded y -> 1e18)
__device__ __align__(16) float g_sx[4][MAXN * MAXP];
__device__ __align__(16) float g_sy[4][MAXN * MAXP];
__device__ unsigned g_minx[MAXN * MAXP];
__device__ unsigned g_miny[MAXN * MAXP];
__device__ float    g_part[MAXN][2][FSPLIT];

// ---- f32x2 packed helpers ------------------------------------------------
static __device__ __forceinline__ u64 pack2(float lo, float hi) {
    u64 r; asm("mov.b64 %0, {%1,%2};" : "=l"(r) : "f"(lo), "f"(hi)); return r;
}
static __device__ __forceinline__ u64 fma2(u64 a, u64 b, u64 c) {
    u64 d; asm("fma.rn.f32x2 %0, %1, %2, %3;" : "=l"(d) : "l"(a), "l"(b), "l"(c)); return d;
}
static __device__ __forceinline__ void unpack2(u64 v, float& lo, float& hi) {
    asm("mov.b64 {%0,%1}, %2;" : "=f"(lo), "=f"(hi) : "l"(v));
}

// Order-preserving float <-> uint mapping
static __device__ __forceinline__ unsigned fkey(float f) {
    unsigned u = __float_as_uint(f);
    return (u & 0x80000000u) ? ~u : (u | 0x80000000u);
}
static __device__ __forceinline__ float finv(unsigned u) {
    unsigned v = (u & 0x80000000u) ? (u ^ 0x80000000u) : ~u;
    return __uint_as_float(v);
}

// ---- pack: AoS xyz -> SoA {x,y,z,h}, init min keys -----------------------
__global__ void pack_kernel(const float* __restrict__ x, const float* __restrict__ y,
                            const int* __restrict__ lens, int n, int p1, int p2) {
    int idx = blockIdx.x * blockDim.x + threadIdx.x;
    if (idx < n * p1) {
        float a = x[3 * idx + 0], b = x[3 * idx + 1], c = x[3 * idx + 2];
        g_sx[0][idx] = a; g_sx[1][idx] = b; g_sx[2][idx] = c;
        g_sx[3][idx] = 0.5f * (a * a + b * b + c * c);
        g_minx[idx] = 0xFFFFFFFFu;
    }
    if (idx < n * p2) {
        int b_ = idx / p2;
        int j  = idx - b_ * p2;
        float a = y[3 * idx + 0], bb = y[3 * idx + 1], c = y[3 * idx + 2];
        float h = 0.5f * (a * a + bb * bb + c * c);
        g_sy[0][idx] = a; g_sy[1][idx] = bb; g_sy[2][idx] = c;
        g_sy[3][idx] = (j < lens[b_]) ? h : 1e18f;   // padded targets never win min
        g_miny[idx] = 0xFFFFFFFFu;
    }
}

// ---- fused both-direction pass ------------------------------------------
// blockIdx.z = batch*2 + dir. dir=0: outer=pred, inner=target. dir=1: outer=target, inner=pred.
// min_j d2 = 2*(h_outer + min_j (h_j - dot_ij)); inner math = 1.5 FFMA2 + 1 FMNMX per pair.
__global__ void __launch_bounds__(BLOCK) pass_kernel(const int* __restrict__ lens,
                                                     int p1, int p2) {
    int zb  = blockIdx.z;
    int b   = zb >> 1;
    int dir = zb & 1;
    int len = __ldg(lens + b);

    int p_out = dir ? p2 : p1;
    int p_in  = dir ? p1 : p2;

    int tb = blockIdx.x * TILE;
    if (tb >= p_out) return;
    if (dir && tb >= len) return;                 // whole outer tile padded (dir1)

    int cb = blockIdx.y * CHUNK;
    int ilim = dir ? p_in : min(p_in, (len + 3) & ~3);   // dir0: clip inner to valid y
    if (cb >= ilim) return;
    int je = min(cb + CHUNK, ilim) >> 2;          // float4 granules
    int jb0 = cb >> 2;

    const float (*ip)[MAXN * MAXP] = dir ? g_sx : g_sy;   // inner SoA
    const float (*op)[MAXN * MAXP] = dir ? g_sy : g_sx;   // outer SoA
    unsigned* mins = dir ? g_miny : g_minx;

    // Outer points: pre-negated, duplicated into both f32x2 lanes.
    int obase = b * p_out + tb + threadIdx.x;
    u64 nx[RPT], ny[RPT], nz[RPT];
    float m[RPT];
#pragma unroll
    for (int r = 0; r < RPT; r++) {
        float a = op[0][obase + r * BLOCK];
        float bb = op[1][obase + r * BLOCK];
        float c = op[2][obase + r * BLOCK];
        nx[r] = pack2(-a, -a);
        ny[r] = pack2(-bb, -bb);
        nz[r] = pack2(-c, -c);
        m[r] = 3.4e38f;
    }

    const float4* __restrict__ PX = (const float4*)&ip[0][b * p_in];
    const float4* __restrict__ PY = (const float4*)&ip[1][b * p_in];
    const float4* __restrict__ PZ = (const float4*)&ip[2][b * p_in];
    const float4* __restrict__ PH = (const float4*)&ip[3][b * p_in];

    for (int jb = jb0; jb < je; ++jb) {
        float4 vx = __ldg(PX + jb);
        float4 vy = __ldg(PY + jb);
        float4 vz = __ldg(PZ + jb);
        float4 vh = __ldg(PH + jb);
        u64 x01 = pack2(vx.x, vx.y), x23 = pack2(vx.z, vx.w);
        u64 y01 = pack2(vy.x, vy.y), y23 = pack2(vy.z, vy.w);
        u64 z01 = pack2(vz.x, vz.y), z23 = pack2(vz.z, vz.w);
        u64 h01 = pack2(vh.x, vh.y), h23 = pack2(vh.z, vh.w);
#pragma unroll
        for (int r = 0; r < RPT; r++) {
            u64 t = fma2(nx[r], x01, h01);
            t = fma2(ny[r], y01, t);
            t = fma2(nz[r], z01, t);
            float lo, hi; unpack2(t, lo, hi);
            m[r] = fminf(m[r], fminf(lo, hi));
            u64 s = fma2(nx[r], x23, h23);
            s = fma2(ny[r], y23, s);
            s = fma2(nz[r], z23, s);
            unpack2(s, lo, hi);
            m[r] = fminf(m[r], fminf(lo, hi));
        }
    }

#pragma unroll
    for (int r = 0; r < RPT; r++)
        atomicMin(&mins[obase + r * BLOCK], fkey(m[r]));  // padded outer rows harmless
}

// ---- finalize stage 1: split partial sums (deterministic ranges) ---------
__global__ void finalize1(const int* __restrict__ lens, int p1, int p2) {
    int b = blockIdx.x, dir = blockIdx.y, split = blockIdx.z;
    int p   = dir ? p2 : p1;
    int lim = dir ? __ldg(lens + b) : p1;
    int per = p / FSPLIT;
    int lo = split * per;
    int hi = min(lo + per, lim);
    const float* hs = dir ? g_sy[3] : g_sx[3];
    const unsigned* mins = dir ? g_miny : g_minx;

    __shared__ float sh[BLOCKF];
    float acc = 0.f;
    for (int i = lo + threadIdx.x; i < hi; i += BLOCKF) {
        float d2 = 2.f * (hs[b * p + i] + finv(mins[b * p + i]));
        acc += fmaxf(d2, 0.f);
    }
    sh[threadIdx.x] = acc;
    __syncthreads();
    for (int s = BLOCKF / 2; s > 0; s >>= 1) {
        if (threadIdx.x < s) sh[threadIdx.x] += sh[threadIdx.x + s];
        __syncthreads();
    }
    if (threadIdx.x == 0) g_part[b][dir][split] = sh[0];
}

// ---- finalize stage 2: fixed-order combine ------------------------------
__global__ void finalize2(float* __restrict__ out, const int* __restrict__ lens,
                          int n, int p1) {
    if (threadIdx.x != 0) return;
    float s = 0.f;
    for (int b = 0; b < n; b++) {
        for (int dir = 0; dir < 2; dir++) {
            float t = 0.f;
            for (int k = 0; k < FSPLIT; k++) t += g_part[b][dir][k];
            s += t / (dir ? (float)lens[b] : (float)p1);
        }
    }
    out[0] = s / (float)n;
}

extern "C" void kernel_launch(void* const* d_in, const int* in_sizes, int n_in,
                              void* d_out, int out_size) {
    const float* x   = (const float*)d_in[0];   // pred_points   [N,P1,3] f32
    const float* y   = (const float*)d_in[1];   // target_points [N,P2,3] f32
    const int*  lens = (const int*)d_in[2];     // target_lengths [N] i32
    // d_in[3] = num_neighbours == 1 (mean over K=1 is identity)

    int n  = in_sizes[2];
    int p1 = in_sizes[0] / (3 * n);
    int p2 = in_sizes[1] / (3 * n);
    int mx = p1 > p2 ? p1 : p2;

    pack_kernel<<<(n * mx + 255) / 256, 256>>>(x, y, lens, n, p1, p2);

    int tiles  = (mx + TILE - 1) / TILE;
    int chunks = (mx + CHUNK - 1) / CHUNK;
    dim3 g(tiles, chunks, n * 2);
    pass_kernel<<<g, BLOCK>>>(lens, p1, p2);

    finalize1<<<dim3(n, 2, FSPLIT), BLOCKF>>>(lens, p1, p2);
    finalize2<<<1, 32>>>((float*)d_out, lens, n, p1);
}